// round 13
// baseline (speedup 1.0000x reference)
#include <cuda_runtime.h>
#include <cuda_fp16.h>
#include <cstdint>

// ---------------- problem constants ----------------
#define Bc 4
#define Lc 8192
#define Dc 512
#define Hc 8
#define DKc 64
#define Ec 65           // DK + PD
#define Fc 520          // H * E
#define FP 544          // padded F (multiple of 32)
#define EHH 72          // padded per-head width (halfs, 144B = 9x16B)
#define NSPLIT 16
#define LCHUNK (Lc / NSPLIT)   // 512

#define ATT_ELEMS  ((size_t)Bc * Lc * Dc)
#define ATTN_ELEMS ((size_t)Bc * Hc * Ec * Ec)
#define BLD ((size_t)Bc * Lc * Dc)

// ---------------- scratch (device globals; no allocs allowed) ----------------
__device__ __half g_Xh[3][BLD];                      // fp16 query/key/value
__device__ __half g_Wh[3][(size_t)Dc * Dc];          // fp16 Wq/Wk/Wv
__device__ __half g_QCh[(size_t)Bc * Lc * FP];       // concat q, fp16, pad zeroed
__device__ __half g_KHh[(size_t)Bc * Hc * Lc * EHH]; // LN'd k, fp16 (rounded once)
__device__ __half g_VHh[(size_t)Bc * Hc * Lc * EHH]; // LN'd v, fp16
__device__ float  g_part[(size_t)Bc * Hc * NSPLIT * Ec * Ec];
__device__ __half g_W2Th[(size_t)Bc * Dc * FP];      // folded fc weights, fp16

// ============================================================================
// helpers
// ============================================================================
__device__ __forceinline__ uint32_t smem_u32(const void* p) {
    uint32_t a;
    asm("{ .reg .u64 t; cvta.to.shared.u64 t, %1; cvt.u32.u64 %0, t; }" : "=r"(a) : "l"(p));
    return a;
}
__device__ __forceinline__ void cp16(uint32_t dst, const void* src) {
    asm volatile("cp.async.ca.shared.global [%0], [%1], 16;" :: "r"(dst), "l"(src));
}
#define CP_COMMIT() asm volatile("cp.async.commit_group;" ::: "memory")
#define CP_WAIT0()  asm volatile("cp.async.wait_group 0;" ::: "memory")
#define CP_WAIT1()  asm volatile("cp.async.wait_group 1;" ::: "memory")

__device__ __forceinline__ void mma_f16(float c[4], const uint32_t a[4], const uint32_t b[2]) {
    asm volatile(
        "mma.sync.aligned.m16n8k16.row.col.f32.f16.f16.f32 "
        "{%0,%1,%2,%3}, {%4,%5,%6,%7}, {%8,%9}, {%0,%1,%2,%3};"
        : "+f"(c[0]), "+f"(c[1]), "+f"(c[2]), "+f"(c[3])
        : "r"(a[0]), "r"(a[1]), "r"(a[2]), "r"(a[3]), "r"(b[0]), "r"(b[1]));
}
#define LDSM_X4(r0, r1, r2, r3, addr) \
    asm volatile("ldmatrix.sync.aligned.m8n8.x4.shared.b16 {%0,%1,%2,%3}, [%4];" \
        : "=r"(r0), "=r"(r1), "=r"(r2), "=r"(r3) : "r"(addr))
#define LDSM_X4_T(r0, r1, r2, r3, addr) \
    asm volatile("ldmatrix.sync.aligned.m8n8.x4.trans.shared.b16 {%0,%1,%2,%3}, [%4];" \
        : "=r"(r0), "=r"(r1), "=r"(r2), "=r"(r3) : "r"(addr))
#define LDSM_X2_T(r0, r1, addr) \
    asm volatile("ldmatrix.sync.aligned.m8n8.x2.trans.shared.b16 {%0,%1}, [%2];" \
        : "=r"(r0), "=r"(r1) : "r"(addr))

// ============================================================================
// fp16 GEMM mainloop: C[M,N] = A[M,K] @ B[N,K]^T, fp32 accum.
// 128x128 CTA tile, 256 thr (8 warps, warp tile 64x32), K-block 32,
// cp.async 3-stage, fragments via ldmatrix.x4.
// ============================================================================
#define SSTRH 40                        // smem row stride in halfs (80B)
#define ATILEH (128 * SSTRH)            // 5120 halfs per operand per stage
#define STAGEH (2 * ATILEH)             // 10240 halfs per stage
#define NSTAGE 3
#define SMEM_MAIN (NSTAGE * STAGEH * 2) // 61440 bytes
#define SMEM_PROJ (128 * 132 * 4)       // 67584 bytes (epilogue staging)

__device__ __forceinline__ void gemm_copy_stage(
    const __half* __restrict__ A, const __half* __restrict__ Bw,
    int lda, int m0, int n0, int kb, uint32_t sbase, int r0, int c)
{
    const int s = kb % NSTAGE;
    const int k0 = kb << 5;
    uint32_t as = sbase + (uint32_t)(s * STAGEH) * 2u;
    uint32_t bs = as + (uint32_t)ATILEH * 2u;
#pragma unroll
    for (int rr = 0; rr < 2; rr++) {
        const int row = r0 + rr * 64;
        uint32_t doff = (uint32_t)(row * SSTRH + c * 8) * 2u;
        cp16(as + doff, A + (size_t)(m0 + row) * lda + k0 + c * 8);
        cp16(bs + doff, Bw + (size_t)(n0 + row) * lda + k0 + c * 8);
    }
}

__device__ __forceinline__ void gemm_mainloop(
    const __half* __restrict__ A, const __half* __restrict__ Bw,
    int lda, int NKB, int m0, int n0,
    uint32_t sbase, float acc[4][4][4])
{
    const int tid = threadIdx.x;
    const int wid = tid >> 5;
    const int lane = tid & 31;
    const int mw = (wid >> 2) * 64;
    const int nw = (wid & 3) * 32;
    const int r0 = tid >> 2;              // copy row 0..63 (+64)
    const int cc = tid & 3;               // copy chunk

    const int rA = (lane & 7) + (lane & 8);
    const int cA = (lane & 16) >> 1;
    const int rB = (lane & 7) + ((lane & 16) >> 1);
    const int cB = (lane & 8);
    const uint32_t aoff = (uint32_t)((mw + rA) * SSTRH + cA) * 2u;
    const uint32_t boff = (uint32_t)((nw + rB) * SSTRH + cB) * 2u;

    gemm_copy_stage(A, Bw, lda, m0, n0, 0, sbase, r0, cc);
    CP_COMMIT();
    gemm_copy_stage(A, Bw, lda, m0, n0, 1, sbase, r0, cc);
    CP_COMMIT();

#pragma unroll 1
    for (int kb = 0; kb < NKB; kb++) {
        if (kb + 1 < NKB) { CP_WAIT1(); } else { CP_WAIT0(); }
        __syncthreads();
        if (kb + 2 < NKB) {
            gemm_copy_stage(A, Bw, lda, m0, n0, kb + 2, sbase, r0, cc);
            CP_COMMIT();
        }

        const uint32_t abase = sbase + (uint32_t)((kb % NSTAGE) * STAGEH) * 2u;
        const uint32_t bbase = abase + (uint32_t)ATILEH * 2u;
#pragma unroll
        for (int kk = 0; kk < 32; kk += 16) {
            uint32_t af[4][4];
#pragma unroll
            for (int i = 0; i < 4; i++)
                LDSM_X4(af[i][0], af[i][1], af[i][2], af[i][3],
                        abase + aoff + (uint32_t)((16 * i) * SSTRH + kk) * 2u);
            uint32_t bf[4][2];
#pragma unroll
            for (int jj = 0; jj < 2; jj++)
                LDSM_X4(bf[2 * jj][0], bf[2 * jj][1], bf[2 * jj + 1][0], bf[2 * jj + 1][1],
                        bbase + boff + (uint32_t)((16 * jj) * SSTRH + kk) * 2u);
#pragma unroll
            for (int i = 0; i < 4; i++)
#pragma unroll
                for (int j = 0; j < 4; j++)
                    mma_f16(acc[i][j], af[i], bf[j]);
        }
    }
}

// ============================================================================
// Kernel X: convert inputs/weights to fp16 (vectorized)
// ============================================================================
__global__ void xcvt(const float* __restrict__ Xq, const float* __restrict__ Xk,
                     const float* __restrict__ Xv)
{
    const int op = blockIdx.y;
    const float* X = (op == 0) ? Xq : (op == 1) ? Xk : Xv;
    const size_t i4 = (size_t)blockIdx.x * 256 + threadIdx.x;
    float4 v = ((const float4*)X)[i4];
    __half2* dst = (__half2*)(g_Xh[op] + i4 * 4);
    dst[0] = __floats2half2_rn(v.x, v.y);
    dst[1] = __floats2half2_rn(v.z, v.w);
}

__global__ void wcvt(const float* __restrict__ Wq, const float* __restrict__ Wk,
                     const float* __restrict__ Wv)
{
    const int op = blockIdx.y;
    const float* W = (op == 0) ? Wq : (op == 1) ? Wk : Wv;
    const size_t i4 = (size_t)blockIdx.x * 256 + threadIdx.x;
    float4 v = ((const float4*)W)[i4];
    __half2* dst = (__half2*)(g_Wh[op] + i4 * 4);
    dst[0] = __floats2half2_rn(v.x, v.y);
    dst[1] = __floats2half2_rn(v.z, v.w);
}

// ============================================================================
// Kernel A: fused projection + LN + concat.  grid (4, 256, 3), 256 thr.
// ============================================================================
#define CSTR 132

__global__ void __launch_bounds__(256, 2)
proj_fused(const float* __restrict__ bq, const float* __restrict__ bk,
           const float* __restrict__ bv,
           const float* __restrict__ gK, const float* __restrict__ betaK,
           const float* __restrict__ gV, const float* __restrict__ betaV,
           const float* __restrict__ pos)
{
    extern __shared__ __align__(16) char smraw[];
    float* smf = (float*)smraw;
    const uint32_t sbase = smem_u32(smraw);
    const int mode = blockIdx.z;
    const __half* A = g_Xh[mode];
    const __half* W = g_Wh[mode];
    const float* bias = (mode == 0) ? bq : (mode == 1) ? bk : bv;
    const float* gamm = (mode == 1) ? gK : gV;
    const float* beta = (mode == 1) ? betaK : betaV;

    const int m0 = blockIdx.y * 128;
    const int n0 = blockIdx.x * 128;

    float acc[4][4][4] = {};
    gemm_mainloop(A, W, Dc, Dc / 32, m0, n0, sbase, acc);

    // ---- stage tile (+bias) into smem as fp32 ----
    __syncthreads();
    const int tid = threadIdx.x;
    const int wid = tid >> 5;
    const int lane = tid & 31;
    const int g = lane >> 2;
    const int t = lane & 3;
    const int mw = (wid >> 2) * 64;
    const int nw = (wid & 3) * 32;

#pragma unroll
    for (int i = 0; i < 4; i++) {
        const int r0 = mw + 16 * i + g;
#pragma unroll
        for (int j = 0; j < 4; j++) {
            const int col = nw + 8 * j + 2 * t;
            float2 bv2 = *(const float2*)(bias + n0 + col);
            smf[r0 * CSTR + col]       = acc[i][j][0] + bv2.x;
            smf[r0 * CSTR + col + 1]   = acc[i][j][1] + bv2.y;
            smf[(r0 + 8) * CSTR + col]     = acc[i][j][2] + bv2.x;
            smf[(r0 + 8) * CSTR + col + 1] = acc[i][j][3] + bv2.y;
        }
    }
    __syncthreads();

    // ---- per-row epilogue: 8 warps x 16 rows ----
    for (int rr = 0; rr < 16; rr++) {
        const int r = wid * 16 + rr;
        const int m = m0 + r;                 // = b*L + l
        const int b = m >> 13, l = m & (Lc - 1);
        const float pv = pos[m];
#pragma unroll
        for (int hh = 0; hh < 2; hh++) {
            const int h = (n0 >> 6) + hh;
            float x0 = smf[r * CSTR + 64 * hh + lane];
            float x1 = smf[r * CSTR + 64 * hh + lane + 32];
            if (mode == 0) {
                __half* qrow = &g_QCh[(size_t)m * FP + h * Ec];
                if (lane == 0) qrow[0] = __float2half_rn(pv);
                qrow[1 + lane] = __float2half_rn(x0);
                qrow[1 + lane + 32] = __float2half_rn(x1);
                if (hh == 1 && n0 == 384 && lane < (FP - Fc))
                    g_QCh[(size_t)m * FP + Fc + lane] = __float2half_rn(0.0f);
            } else {
                float s = x0 + x1, sq = x0 * x0 + x1 * x1;
#pragma unroll
                for (int off = 16; off; off >>= 1) {
                    s  += __shfl_xor_sync(0xffffffffu, s,  off);
                    sq += __shfl_xor_sync(0xffffffffu, sq, off);
                }
                float mean = s * (1.0f / 64.0f);
                float var = sq * (1.0f / 64.0f) - mean * mean;
                float rstd = rsqrtf(var + 1e-5f);
                float y0 = (x0 - mean) * rstd * gamm[h * DKc + lane] + beta[h * DKc + lane];
                float y1 = (x1 - mean) * rstd * gamm[h * DKc + lane + 32] + beta[h * DKc + lane + 32];
                __half* orow = ((mode == 1) ? g_KHh : g_VHh) +
                               (((size_t)b * Hc + h) * Lc + l) * EHH;
                if (lane == 0) orow[0] = __float2half_rn(pv);
                orow[1 + lane] = __float2half_rn(y0);
                orow[1 + lane + 32] = __float2half_rn(y1);
                if (lane < (EHH - Ec)) orow[Ec + lane] = __float2half_rn(0.0f); // pad 65..71
            }
        }
    }
}

// ============================================================================
// Kernel B: attn partials via fp16 MMA + ldmatrix.trans.
// Smem tiles S_k/S_v: [l][d] fp16, stride 96 (cols 72..95 pre-zeroed, cp.async
// writes only cols 0..71).  A = K^T via x4.trans; B = V via x4/x2.trans.
// Tile 96x96, 8 warps (2m x 4n), warp 48x24.  fp32 accum, deterministic.
// ============================================================================
#define AST 96                          // smem row stride (halfs)
#define ATILE_H (32 * AST)              // 3072 halfs per operand per stage
#define ASTG (2 * ATILE_H)              // 6144 halfs per stage
#define ANST 3
#define SMEM_ATTN (ANST * ASTG * 2)     // 36864 bytes

__global__ void __launch_bounds__(256, 2)
attn_mma()
{
    extern __shared__ __align__(16) __half smha[];
    const uint32_t sbase = smem_u32(smha);
    const int split = blockIdx.x, h = blockIdx.y, b = blockIdx.z;
    const int tid = threadIdx.x;
    const int wid = tid >> 5, lane = tid & 31;
    const int g = lane >> 2, t = lane & 3;
    const int mw = (wid >> 2) * 48;       // 2 warp-rows of 48 (d)
    const int nw = (wid & 3) * 24;        // 4 warp-cols of 24 (e)
    const int NKB = LCHUNK / 32;          // 16

    const __half* Kb = g_KHh + (((size_t)b * Hc + h) * Lc + (size_t)split * LCHUNK) * EHH;
    const __half* Vb = g_VHh + (((size_t)b * Hc + h) * Lc + (size_t)split * LCHUNK) * EHH;

    // zero ALL smem once (pad cols stay zero forever; data cols overwritten)
    for (int i = tid; i < ANST * ASTG / 8; i += 256)
        ((uint4*)smha)[i] = make_uint4(0, 0, 0, 0);
    __syncthreads();

    auto issue = [&](int kb) {
        const int s = kb % ANST;
        const int l0 = kb << 5;
        uint32_t base = sbase + (uint32_t)(s * ASTG) * 2u;
#pragma unroll
        for (int c = 0; c < 3; c++) {
            int idx = tid + (c << 8);
            if (idx < 576) {                       // 32 rows x 9 chunks x 2 ops
                int op = idx >= 288;
                int i2 = op ? idx - 288 : idx;
                int row = i2 / 9, ch = i2 % 9;
                const __half* src = (op ? Vb : Kb) + (size_t)(l0 + row) * EHH + ch * 8;
                cp16(base + (uint32_t)(op * ATILE_H + row * AST + ch * 8) * 2u, src);
            }
        }
        CP_COMMIT();
    };

    issue(0);
    issue(1);

    // ldmatrix.trans per-lane address components
    const int arow = (lane & 7) + ((lane & 16) >> 1);   // A: k-row offset
    const int acol = (lane & 8);                        // A: d offset
    const int brow = (lane & 7) + (lane & 8);           // B x4: k-row offset
    const int bcol = (lane & 16) >> 1;                  // B x4: e offset
    const int brow2 = (lane & 7) + (lane & 8);          // B x2 (lanes 0-15 used)

    float acc[3][3][4] = {};

#pragma unroll 1
    for (int kb = 0; kb < NKB; kb++) {
        if (kb + 1 < NKB) { CP_WAIT1(); } else { CP_WAIT0(); }
        __syncthreads();
        if (kb + 2 < NKB) issue(kb + 2);

        const uint32_t kbase = sbase + (uint32_t)((kb % ANST) * ASTG) * 2u;
        const uint32_t vbase = kbase + (uint32_t)ATILE_H * 2u;
#pragma unroll
        for (int kk = 0; kk < 32; kk += 16) {
            uint32_t af[3][4];
#pragma unroll
            for (int i = 0; i < 3; i++) {
                const int d0 = mw + 16 * i;
                LDSM_X4_T(af[i][0], af[i][1], af[i][2], af[i][3],
                          kbase + (uint32_t)((kk + arow) * AST + d0 + acol) * 2u);
            }
            uint32_t bf[3][2];
            LDSM_X4_T(bf[0][0], bf[0][1], bf[1][0], bf[1][1],
                      vbase + (uint32_t)((kk + brow) * AST + nw + bcol) * 2u);
            LDSM_X2_T(bf[2][0], bf[2][1],
                      vbase + (uint32_t)((kk + brow2) * AST + nw + 16) * 2u);
#pragma unroll
            for (int i = 0; i < 3; i++)
#pragma unroll
                for (int j = 0; j < 3; j++)
                    mma_f16(acc[i][j], af[i], bf[j]);
        }
    }

    // store partials (valid region 65x65 only)
    float* out = &g_part[(((size_t)b * Hc + h) * NSPLIT + split) * Ec * Ec];
#pragma unroll
    for (int i = 0; i < 3; i++) {
        const int m = mw + 16 * i + g;
#pragma unroll
        for (int j = 0; j < 3; j++) {
            const int n = nw + 8 * j + 2 * t;
            if (m < Ec) {
                if (n < Ec)     out[m * Ec + n]     = acc[i][j][0];
                if (n + 1 < Ec) out[m * Ec + n + 1] = acc[i][j][1];
            }
            if (m + 8 < Ec) {
                if (n < Ec)     out[(m + 8) * Ec + n]     = acc[i][j][2];
                if (n + 1 < Ec) out[(m + 8) * Ec + n + 1] = acc[i][j][3];
            }
        }
    }
}

// ============================================================================
// Kernel C: reduce partials, scale by 1/L
// ============================================================================
__global__ void attn_reduce(float* __restrict__ attn_out)
{
    const size_t idx = (size_t)blockIdx.x * blockDim.x + threadIdx.x;
    if (idx >= ATTN_ELEMS) return;
    const size_t bh = idx / (Ec * Ec);
    const size_t de = idx % (Ec * Ec);
    float s = 0.0f;
#pragma unroll
    for (int sp = 0; sp < NSPLIT; sp++)
        s += g_part[(bh * NSPLIT + sp) * (Ec * Ec) + de];
    attn_out[idx] = s * (1.0f / (float)Lc);
}

// ============================================================================
// Kernel D: W2Th[b,o,h*65+d] = sum_e attn[b,h,d,e]*fcW[o,h*65+e]   (fp16 out)
// ============================================================================
__global__ void __launch_bounds__(256)
w2t_kernel(const float* __restrict__ attn, const float* __restrict__ fcW)
{
    const int og = blockIdx.x;          // 0..7 (64 o's each)
    const int bh = blockIdx.y;          // 0..31
    const int b = bh >> 3, h = bh & 7;
    __shared__ float sa[Ec * 68];       // sa[e*68 + d] = attn[d][e]  (transposed)
    __shared__ float sw[64 * 66];       // sw[o*66 + e] = fcW row
    const int tid = threadIdx.x;

    for (int i = tid; i < Ec * Ec; i += 256) {
        int d = i / Ec, e = i % Ec;
        sa[e * 68 + d] = attn[((size_t)bh * Ec + d) * Ec + e];
    }
    for (int i = tid; i < 64 * Ec; i += 256) {
        int o = i / Ec, e = i % Ec;
        sw[o * 66 + e] = fcW[(size_t)(og * 64 + o) * Fc + h * Ec + e];
    }
    __syncthreads();

    for (int idx = tid; idx < 64 * Ec; idx += 256) {
        int o = idx / Ec, d = idx % Ec;
        const float* wr = &sw[o * 66];
        float s = 0.0f;
#pragma unroll
        for (int e = 0; e < Ec; e++) s += wr[e] * sa[e * 68 + d];
        g_W2Th[((size_t)b * Dc + og * 64 + o) * FP + h * Ec + d] = __float2half_rn(s);
    }
    if (h == 0) {
        for (int i = tid; i < 64 * (FP - Fc); i += 256) {
            int o = og * 64 + i / (FP - Fc), cc = Fc + i % (FP - Fc);
            g_W2Th[((size_t)b * Dc + o) * FP + cc] = __float2half_rn(0.0f);
        }
    }
}

// ============================================================================
// Kernel E: out[b] = QCh[b] @ W2Th[b]^T + fcb.  grid (4, 64, 4), 256 thr.
// ============================================================================
__global__ void __launch_bounds__(256, 2)
out_gemm(const float* __restrict__ fcb, float* __restrict__ out)
{
    extern __shared__ __align__(16) char smraw[];
    const uint32_t sbase = smem_u32(smraw);
    const int b = blockIdx.z;
    const __half* A  = g_QCh + (size_t)b * Lc * FP;
    const __half* Bw = g_W2Th + (size_t)b * Dc * FP;
    float* C = out + (size_t)b * Lc * Dc;

    const int m0 = blockIdx.y * 128;
    const int n0 = blockIdx.x * 128;

    float acc[4][4][4] = {};
    gemm_mainloop(A, Bw, FP, FP / 32, m0, n0, sbase, acc);

    const int tid = threadIdx.x;
    const int wid = tid >> 5;
    const int lane = tid & 31;
    const int g = lane >> 2;
    const int t = lane & 3;
    const int mw = (wid >> 2) * 64;
    const int nw = (wid & 3) * 32;

#pragma unroll
    for (int i = 0; i < 4; i++) {
        const int row0 = m0 + mw + 16 * i + g;
#pragma unroll
        for (int j = 0; j < 4; j++) {
            const int col = n0 + nw + 8 * j + 2 * t;
            float2 bv = *(const float2*)(fcb + col);
            float2 o0, o1;
            o0.x = acc[i][j][0] + bv.x;  o0.y = acc[i][j][1] + bv.y;
            o1.x = acc[i][j][2] + bv.x;  o1.y = acc[i][j][3] + bv.y;
            *(float2*)(C + (size_t)row0 * Dc + col) = o0;
            *(float2*)(C + (size_t)(row0 + 8) * Dc + col) = o1;
        }
    }
}

// ============================================================================
// launch
// ============================================================================
extern "C" void kernel_launch(void* const* d_in, const int* in_sizes, int n_in,
                              void* d_out, int out_size)
{
    const float* query = (const float*)d_in[0];
    const float* key   = (const float*)d_in[1];
    const float* value = (const float*)d_in[2];
    const float* pos   = (const float*)d_in[3];
    const float* Wq    = (const float*)d_in[4];
    const float* bq    = (const float*)d_in[5];
    const float* Wk    = (const float*)d_in[6];
    const float* bk    = (const float*)d_in[7];
    const float* Wv    = (const float*)d_in[8];
    const float* bv    = (const float*)d_in[9];
    const float* gK    = (const float*)d_in[10];
    const float* betaK = (const float*)d_in[11];
    const float* gV    = (const float*)d_in[12];
    const float* betaV = (const float*)d_in[13];
    const float* fcW   = (const float*)d_in[14];
    const float* fcb   = (const float*)d_in[15];

    float* att_out  = (float*)d_out;
    float* attn_out = att_out + ATT_ELEMS;

    cudaFuncSetAttribute(proj_fused, cudaFuncAttributeMaxDynamicSharedMemorySize, SMEM_PROJ);
    cudaFuncSetAttribute(out_gemm,  cudaFuncAttributeMaxDynamicSharedMemorySize, SMEM_MAIN);
    cudaFuncSetAttribute(attn_mma,  cudaFuncAttributeMaxDynamicSharedMemorySize, SMEM_ATTN);

    // 0) convert inputs + weights to fp16
    xcvt<<<dim3((unsigned)(BLD / 4 / 256), 3), 256>>>(query, key, value);
    wcvt<<<dim3(Dc * Dc / 4 / 256, 3), 256>>>(Wq, Wk, Wv);
    // 1) fused projections + LN + concat (fp16 MMA, fp32 accum)
    proj_fused<<<dim3(4, 256, 3), 256, SMEM_PROJ>>>(bq, bk, bv,
                                                     gK, betaK, gV, betaV, pos);
    // 2) attn partials via fp16 MMA + ldmatrix.trans (deterministic)
    attn_mma<<<dim3(NSPLIT, Hc, Bc), 256, SMEM_ATTN>>>();
    // 3) reduce + scale -> attn output
    attn_reduce<<<(unsigned)((ATTN_ELEMS + 255) / 256), 256>>>(attn_out);
    // 4) fold attn into fc weights (fp16 out)
    w2t_kernel<<<dim3(8, Bc * Hc), 256>>>(attn_out, fcW);
    // 5) output GEMM (fp16 MMA), batched over z
    out_gemm<<<dim3(4, 64, Bc), 256, SMEM_MAIN>>>(fcb, att_out);
}

// round 14
// speedup vs baseline: 1.0672x; 1.0672x over previous
#include <cuda_runtime.h>
#include <cuda_fp16.h>
#include <cstdint>

// ---------------- problem constants ----------------
#define Bc 4
#define Lc 8192
#define Dc 512
#define Hc 8
#define DKc 64
#define Ec 65           // DK + PD
#define Fc 520          // H * E
#define FP 544          // padded F (multiple of 32)
#define EHH 72          // padded per-head width (halfs, 144B = 9x16B)
#define NSPLIT 16
#define LCHUNK (Lc / NSPLIT)   // 512

#define ATT_ELEMS  ((size_t)Bc * Lc * Dc)
#define ATTN_ELEMS ((size_t)Bc * Hc * Ec * Ec)
#define BLD ((size_t)Bc * Lc * Dc)

// ---------------- scratch (device globals; no allocs allowed) ----------------
__device__ __half g_Xh[3][BLD];                      // fp16 query/key/value
__device__ __half g_Wh[3][(size_t)Dc * Dc];          // fp16 Wq/Wk/Wv
__device__ __half g_QCh[(size_t)Bc * Lc * FP];       // concat q, fp16, pad zeroed
__device__ __half g_KHh[(size_t)Bc * Hc * Lc * EHH]; // LN'd k, fp16 (rounded once)
__device__ __half g_VHh[(size_t)Bc * Hc * Lc * EHH]; // LN'd v, fp16
__device__ float  g_part[(size_t)Bc * Hc * NSPLIT * Ec * Ec];
__device__ __half g_W2Th[(size_t)Bc * Dc * FP];      // folded fc weights, fp16

// ============================================================================
// helpers
// ============================================================================
__device__ __forceinline__ uint32_t smem_u32(const void* p) {
    uint32_t a;
    asm("{ .reg .u64 t; cvta.to.shared.u64 t, %1; cvt.u32.u64 %0, t; }" : "=r"(a) : "l"(p));
    return a;
}
__device__ __forceinline__ void cp16(uint32_t dst, const void* src) {
    asm volatile("cp.async.ca.shared.global [%0], [%1], 16;" :: "r"(dst), "l"(src));
}
#define CP_COMMIT() asm volatile("cp.async.commit_group;" ::: "memory")
#define CP_WAIT0()  asm volatile("cp.async.wait_group 0;" ::: "memory")
#define CP_WAIT1()  asm volatile("cp.async.wait_group 1;" ::: "memory")

__device__ __forceinline__ void mma_f16(float c[4], const uint32_t a[4], const uint32_t b[2]) {
    asm volatile(
        "mma.sync.aligned.m16n8k16.row.col.f32.f16.f16.f32 "
        "{%0,%1,%2,%3}, {%4,%5,%6,%7}, {%8,%9}, {%0,%1,%2,%3};"
        : "+f"(c[0]), "+f"(c[1]), "+f"(c[2]), "+f"(c[3])
        : "r"(a[0]), "r"(a[1]), "r"(a[2]), "r"(a[3]), "r"(b[0]), "r"(b[1]));
}
#define LDSM_X4(r0, r1, r2, r3, addr) \
    asm volatile("ldmatrix.sync.aligned.m8n8.x4.shared.b16 {%0,%1,%2,%3}, [%4];" \
        : "=r"(r0), "=r"(r1), "=r"(r2), "=r"(r3) : "r"(addr))
#define LDSM_X4_T(r0, r1, r2, r3, addr) \
    asm volatile("ldmatrix.sync.aligned.m8n8.x4.trans.shared.b16 {%0,%1,%2,%3}, [%4];" \
        : "=r"(r0), "=r"(r1), "=r"(r2), "=r"(r3) : "r"(addr))
#define LDSM_X2_T(r0, r1, addr) \
    asm volatile("ldmatrix.sync.aligned.m8n8.x2.trans.shared.b16 {%0,%1}, [%2];" \
        : "=r"(r0), "=r"(r1) : "r"(addr))

// ============================================================================
// fp16 GEMM mainloop: C[M,N] = A[M,K] @ B[N,K]^T, fp32 accum.
// 128x128 CTA tile, 256 thr (8 warps, warp tile 64x32), K-block 32,
// cp.async 3-stage, fragments via ldmatrix.x4.
// ============================================================================
#define SSTRH 40                        // smem row stride in halfs (80B)
#define ATILEH (128 * SSTRH)            // 5120 halfs per operand per stage
#define STAGEH (2 * ATILEH)             // 10240 halfs per stage
#define NSTAGE 3
#define SMEM_MAIN (NSTAGE * STAGEH * 2) // 61440 bytes
#define SMEM_PROJ (128 * 132 * 4)       // 67584 bytes (epilogue staging)

__device__ __forceinline__ void gemm_copy_stage(
    const __half* __restrict__ A, const __half* __restrict__ Bw,
    int lda, int m0, int n0, int kb, uint32_t sbase, int r0, int c)
{
    const int s = kb % NSTAGE;
    const int k0 = kb << 5;
    uint32_t as = sbase + (uint32_t)(s * STAGEH) * 2u;
    uint32_t bs = as + (uint32_t)ATILEH * 2u;
#pragma unroll
    for (int rr = 0; rr < 2; rr++) {
        const int row = r0 + rr * 64;
        uint32_t doff = (uint32_t)(row * SSTRH + c * 8) * 2u;
        cp16(as + doff, A + (size_t)(m0 + row) * lda + k0 + c * 8);
        cp16(bs + doff, Bw + (size_t)(n0 + row) * lda + k0 + c * 8);
    }
}

__device__ __forceinline__ void gemm_mainloop(
    const __half* __restrict__ A, const __half* __restrict__ Bw,
    int lda, int NKB, int m0, int n0,
    uint32_t sbase, float acc[4][4][4])
{
    const int tid = threadIdx.x;
    const int wid = tid >> 5;
    const int lane = tid & 31;
    const int mw = (wid >> 2) * 64;
    const int nw = (wid & 3) * 32;
    const int r0 = tid >> 2;              // copy row 0..63 (+64)
    const int cc = tid & 3;               // copy chunk

    const int rA = (lane & 7) + (lane & 8);
    const int cA = (lane & 16) >> 1;
    const int rB = (lane & 7) + ((lane & 16) >> 1);
    const int cB = (lane & 8);
    const uint32_t aoff = (uint32_t)((mw + rA) * SSTRH + cA) * 2u;
    const uint32_t boff = (uint32_t)((nw + rB) * SSTRH + cB) * 2u;

    gemm_copy_stage(A, Bw, lda, m0, n0, 0, sbase, r0, cc);
    CP_COMMIT();
    gemm_copy_stage(A, Bw, lda, m0, n0, 1, sbase, r0, cc);
    CP_COMMIT();

#pragma unroll 1
    for (int kb = 0; kb < NKB; kb++) {
        if (kb + 1 < NKB) { CP_WAIT1(); } else { CP_WAIT0(); }
        __syncthreads();
        if (kb + 2 < NKB) {
            gemm_copy_stage(A, Bw, lda, m0, n0, kb + 2, sbase, r0, cc);
            CP_COMMIT();
        }

        const uint32_t abase = sbase + (uint32_t)((kb % NSTAGE) * STAGEH) * 2u;
        const uint32_t bbase = abase + (uint32_t)ATILEH * 2u;
#pragma unroll
        for (int kk = 0; kk < 32; kk += 16) {
            uint32_t af[4][4];
#pragma unroll
            for (int i = 0; i < 4; i++)
                LDSM_X4(af[i][0], af[i][1], af[i][2], af[i][3],
                        abase + aoff + (uint32_t)((16 * i) * SSTRH + kk) * 2u);
            uint32_t bf[4][2];
#pragma unroll
            for (int jj = 0; jj < 2; jj++)
                LDSM_X4(bf[2 * jj][0], bf[2 * jj][1], bf[2 * jj + 1][0], bf[2 * jj + 1][1],
                        bbase + boff + (uint32_t)((16 * jj) * SSTRH + kk) * 2u);
#pragma unroll
            for (int i = 0; i < 4; i++)
#pragma unroll
                for (int j = 0; j < 4; j++)
                    mma_f16(acc[i][j], af[i], bf[j]);
        }
    }
}

// ============================================================================
// Kernel X: convert inputs/weights to fp16 (vectorized)
// ============================================================================
__global__ void xcvt(const float* __restrict__ Xq, const float* __restrict__ Xk,
                     const float* __restrict__ Xv)
{
    const int op = blockIdx.y;
    const float* X = (op == 0) ? Xq : (op == 1) ? Xk : Xv;
    const size_t i4 = (size_t)blockIdx.x * 256 + threadIdx.x;
    float4 v = ((const float4*)X)[i4];
    __half2* dst = (__half2*)(g_Xh[op] + i4 * 4);
    dst[0] = __floats2half2_rn(v.x, v.y);
    dst[1] = __floats2half2_rn(v.z, v.w);
}

__global__ void wcvt(const float* __restrict__ Wq, const float* __restrict__ Wk,
                     const float* __restrict__ Wv)
{
    const int op = blockIdx.y;
    const float* W = (op == 0) ? Wq : (op == 1) ? Wk : Wv;
    const size_t i4 = (size_t)blockIdx.x * 256 + threadIdx.x;
    float4 v = ((const float4*)W)[i4];
    __half2* dst = (__half2*)(g_Wh[op] + i4 * 4);
    dst[0] = __floats2half2_rn(v.x, v.y);
    dst[1] = __floats2half2_rn(v.z, v.w);
}

// ============================================================================
// Kernel A: fused projection + LN + concat.  grid (4, 256, 3), 256 thr.
// ============================================================================
#define CSTR 132

__global__ void __launch_bounds__(256, 2)
proj_fused(const float* __restrict__ bq, const float* __restrict__ bk,
           const float* __restrict__ bv,
           const float* __restrict__ gK, const float* __restrict__ betaK,
           const float* __restrict__ gV, const float* __restrict__ betaV,
           const float* __restrict__ pos)
{
    extern __shared__ __align__(16) char smraw[];
    float* smf = (float*)smraw;
    const uint32_t sbase = smem_u32(smraw);
    const int mode = blockIdx.z;
    const __half* A = g_Xh[mode];
    const __half* W = g_Wh[mode];
    const float* bias = (mode == 0) ? bq : (mode == 1) ? bk : bv;
    const float* gamm = (mode == 1) ? gK : gV;
    const float* beta = (mode == 1) ? betaK : betaV;

    const int m0 = blockIdx.y * 128;
    const int n0 = blockIdx.x * 128;

    float acc[4][4][4] = {};
    gemm_mainloop(A, W, Dc, Dc / 32, m0, n0, sbase, acc);

    // ---- stage tile (+bias) into smem as fp32 ----
    __syncthreads();
    const int tid = threadIdx.x;
    const int wid = tid >> 5;
    const int lane = tid & 31;
    const int g = lane >> 2;
    const int t = lane & 3;
    const int mw = (wid >> 2) * 64;
    const int nw = (wid & 3) * 32;

#pragma unroll
    for (int i = 0; i < 4; i++) {
        const int r0 = mw + 16 * i + g;
#pragma unroll
        for (int j = 0; j < 4; j++) {
            const int col = nw + 8 * j + 2 * t;
            float2 bv2 = *(const float2*)(bias + n0 + col);
            smf[r0 * CSTR + col]       = acc[i][j][0] + bv2.x;
            smf[r0 * CSTR + col + 1]   = acc[i][j][1] + bv2.y;
            smf[(r0 + 8) * CSTR + col]     = acc[i][j][2] + bv2.x;
            smf[(r0 + 8) * CSTR + col + 1] = acc[i][j][3] + bv2.y;
        }
    }
    __syncthreads();

    // ---- per-row epilogue: 8 warps x 16 rows ----
    for (int rr = 0; rr < 16; rr++) {
        const int r = wid * 16 + rr;
        const int m = m0 + r;                 // = b*L + l
        const int b = m >> 13, l = m & (Lc - 1);
        const float pv = pos[m];
#pragma unroll
        for (int hh = 0; hh < 2; hh++) {
            const int h = (n0 >> 6) + hh;
            float x0 = smf[r * CSTR + 64 * hh + lane];
            float x1 = smf[r * CSTR + 64 * hh + lane + 32];
            if (mode == 0) {
                __half* qrow = &g_QCh[(size_t)m * FP + h * Ec];
                if (lane == 0) qrow[0] = __float2half_rn(pv);
                qrow[1 + lane] = __float2half_rn(x0);
                qrow[1 + lane + 32] = __float2half_rn(x1);
                if (hh == 1 && n0 == 384 && lane < (FP - Fc))
                    g_QCh[(size_t)m * FP + Fc + lane] = __float2half_rn(0.0f);
            } else {
                float s = x0 + x1, sq = x0 * x0 + x1 * x1;
#pragma unroll
                for (int off = 16; off; off >>= 1) {
                    s  += __shfl_xor_sync(0xffffffffu, s,  off);
                    sq += __shfl_xor_sync(0xffffffffu, sq, off);
                }
                float mean = s * (1.0f / 64.0f);
                float var = sq * (1.0f / 64.0f) - mean * mean;
                float rstd = rsqrtf(var + 1e-5f);
                float y0 = (x0 - mean) * rstd * gamm[h * DKc + lane] + beta[h * DKc + lane];
                float y1 = (x1 - mean) * rstd * gamm[h * DKc + lane + 32] + beta[h * DKc + lane + 32];
                __half* orow = ((mode == 1) ? g_KHh : g_VHh) +
                               (((size_t)b * Hc + h) * Lc + l) * EHH;
                if (lane == 0) orow[0] = __float2half_rn(pv);
                orow[1 + lane] = __float2half_rn(y0);
                orow[1 + lane + 32] = __float2half_rn(y1);
                if (lane < (EHH - Ec)) orow[Ec + lane] = __float2half_rn(0.0f); // pad 65..71
            }
        }
    }
}

// ============================================================================
// Kernel B: attn partials via fp16 MMA + ldmatrix.trans, XOR-swizzled smem.
// Row pitch 256B (16 chunks of 16B); logical chunk c of row l stored at
// physical chunk c ^ (l&7) -> trans ldmatrix reads 8 distinct banksets.
// Logical cols 72..95 never written (pre-zeroed once).  Tile 96x96, 8 warps.
// fp32 accum, fixed order -> deterministic.
// ============================================================================
#define AST 128                         // smem row pitch (halfs) = 256B
#define ATILE_H (32 * AST)              // 4096 halfs per operand per stage
#define ASTG (2 * ATILE_H)              // 8192 halfs per stage
#define ANST 3
#define SMEM_ATTN (ANST * ASTG * 2)     // 49152 bytes

__global__ void __launch_bounds__(256, 2)
attn_mma()
{
    extern __shared__ __align__(16) __half smha[];
    const uint32_t sbase = smem_u32(smha);
    const int split = blockIdx.x, h = blockIdx.y, b = blockIdx.z;
    const int tid = threadIdx.x;
    const int wid = tid >> 5, lane = tid & 31;
    const int g = lane >> 2, t = lane & 3;
    const int mw = (wid >> 2) * 48;       // 2 warp-rows of 48 (d)
    const int nw = (wid & 3) * 24;        // 4 warp-cols of 24 (e)
    const int NKB = LCHUNK / 32;          // 16
    const int s7 = lane & 7;              // swizzle key: (kk+row)&7 == lane&7 always

    const __half* Kb = g_KHh + (((size_t)b * Hc + h) * Lc + (size_t)split * LCHUNK) * EHH;
    const __half* Vb = g_VHh + (((size_t)b * Hc + h) * Lc + (size_t)split * LCHUNK) * EHH;

    // zero ALL smem once (pad chunks stay zero forever; data chunks overwritten)
    for (int i = tid; i < ANST * ASTG / 8; i += 256)
        ((uint4*)smha)[i] = make_uint4(0, 0, 0, 0);
    __syncthreads();

    auto issue = [&](int kb) {
        const int s = kb % ANST;
        const int l0 = kb << 5;
        uint32_t base = sbase + (uint32_t)(s * ASTG) * 2u;
#pragma unroll
        for (int c = 0; c < 3; c++) {
            int idx = tid + (c << 8);
            if (idx < 576) {                       // 32 rows x 9 chunks x 2 ops
                int op = idx >= 288;
                int i2 = op ? idx - 288 : idx;
                int row = i2 / 9, ch = i2 % 9;
                const __half* src = (op ? Vb : Kb) + (size_t)(l0 + row) * EHH + ch * 8;
                uint32_t dst = base + (uint32_t)(op * ATILE_H + row * AST) * 2u
                             + (uint32_t)((ch ^ (row & 7)) * 16);
                cp16(dst, src);
            }
        }
        CP_COMMIT();
    };

    issue(0);
    issue(1);

    // ldmatrix.trans per-lane row offsets
    const int arow = (lane & 7) + ((lane & 16) >> 1);   // A rows: kk + 0..15
    const int acol = (lane & 8);                        // A d offset: 0 or 8
    const int brow = (lane & 7) + (lane & 8);           // B x4 rows
    const int bcol = (lane & 16) >> 1;                  // B x4 e offset: 0 or 8

    // physical chunk offsets (bytes) after swizzle — constant per lane
    uint32_t achk[3];
#pragma unroll
    for (int i = 0; i < 3; i++)
        achk[i] = (uint32_t)((((mw + 16 * i + acol) >> 3) ^ s7) * 16);
    const uint32_t bchk4 = (uint32_t)((((nw + bcol) >> 3) ^ s7) * 16);
    const uint32_t bchk2 = (uint32_t)((((nw + 16) >> 3) ^ s7) * 16);

    float acc[3][3][4] = {};

#pragma unroll 1
    for (int kb = 0; kb < NKB; kb++) {
        if (kb + 1 < NKB) { CP_WAIT1(); } else { CP_WAIT0(); }
        __syncthreads();
        if (kb + 2 < NKB) issue(kb + 2);

        const uint32_t kbase = sbase + (uint32_t)((kb % ANST) * ASTG) * 2u;
        const uint32_t vbase = kbase + (uint32_t)ATILE_H * 2u;
#pragma unroll
        for (int kk = 0; kk < 32; kk += 16) {
            uint32_t af[3][4];
#pragma unroll
            for (int i = 0; i < 3; i++)
                LDSM_X4_T(af[i][0], af[i][1], af[i][2], af[i][3],
                          kbase + (uint32_t)((kk + arow) * AST) * 2u + achk[i]);
            uint32_t bf[3][2];
            LDSM_X4_T(bf[0][0], bf[0][1], bf[1][0], bf[1][1],
                      vbase + (uint32_t)((kk + brow) * AST) * 2u + bchk4);
            LDSM_X2_T(bf[2][0], bf[2][1],
                      vbase + (uint32_t)((kk + brow) * AST) * 2u + bchk2);
#pragma unroll
            for (int i = 0; i < 3; i++)
#pragma unroll
                for (int j = 0; j < 3; j++)
                    mma_f16(acc[i][j], af[i], bf[j]);
        }
    }

    // store partials (valid region 65x65 only)
    float* out = &g_part[(((size_t)b * Hc + h) * NSPLIT + split) * Ec * Ec];
#pragma unroll
    for (int i = 0; i < 3; i++) {
        const int m = mw + 16 * i + g;
#pragma unroll
        for (int j = 0; j < 3; j++) {
            const int n = nw + 8 * j + 2 * t;
            if (m < Ec) {
                if (n < Ec)     out[m * Ec + n]     = acc[i][j][0];
                if (n + 1 < Ec) out[m * Ec + n + 1] = acc[i][j][1];
            }
            if (m + 8 < Ec) {
                if (n < Ec)     out[(m + 8) * Ec + n]     = acc[i][j][2];
                if (n + 1 < Ec) out[(m + 8) * Ec + n + 1] = acc[i][j][3];
            }
        }
    }
}

// ============================================================================
// Kernel C: reduce partials, scale by 1/L
// ============================================================================
__global__ void attn_reduce(float* __restrict__ attn_out)
{
    const size_t idx = (size_t)blockIdx.x * blockDim.x + threadIdx.x;
    if (idx >= ATTN_ELEMS) return;
    const size_t bh = idx / (Ec * Ec);
    const size_t de = idx % (Ec * Ec);
    float s = 0.0f;
#pragma unroll
    for (int sp = 0; sp < NSPLIT; sp++)
        s += g_part[(bh * NSPLIT + sp) * (Ec * Ec) + de];
    attn_out[idx] = s * (1.0f / (float)Lc);
}

// ============================================================================
// Kernel D: W2Th[b,o,h*65+d] = sum_e attn[b,h,d,e]*fcW[o,h*65+e]   (fp16 out)
// ============================================================================
__global__ void __launch_bounds__(256)
w2t_kernel(const float* __restrict__ attn, const float* __restrict__ fcW)
{
    const int og = blockIdx.x;          // 0..7 (64 o's each)
    const int bh = blockIdx.y;          // 0..31
    const int b = bh >> 3, h = bh & 7;
    __shared__ float sa[Ec * 68];       // sa[e*68 + d] = attn[d][e]  (transposed)
    __shared__ float sw[64 * 66];       // sw[o*66 + e] = fcW row
    const int tid = threadIdx.x;

    for (int i = tid; i < Ec * Ec; i += 256) {
        int d = i / Ec, e = i % Ec;
        sa[e * 68 + d] = attn[((size_t)bh * Ec + d) * Ec + e];
    }
    for (int i = tid; i < 64 * Ec; i += 256) {
        int o = i / Ec, e = i % Ec;
        sw[o * 66 + e] = fcW[(size_t)(og * 64 + o) * Fc + h * Ec + e];
    }
    __syncthreads();

    for (int idx = tid; idx < 64 * Ec; idx += 256) {
        int o = idx / Ec, d = idx % Ec;
        const float* wr = &sw[o * 66];
        float s = 0.0f;
#pragma unroll
        for (int e = 0; e < Ec; e++) s += wr[e] * sa[e * 68 + d];
        g_W2Th[((size_t)b * Dc + og * 64 + o) * FP + h * Ec + d] = __float2half_rn(s);
    }
    if (h == 0) {
        for (int i = tid; i < 64 * (FP - Fc); i += 256) {
            int o = og * 64 + i / (FP - Fc), cc = Fc + i % (FP - Fc);
            g_W2Th[((size_t)b * Dc + o) * FP + cc] = __float2half_rn(0.0f);
        }
    }
}

// ============================================================================
// Kernel E: out[b] = QCh[b] @ W2Th[b]^T + fcb.  grid (4, 64, 4), 256 thr.
// ============================================================================
__global__ void __launch_bounds__(256, 2)
out_gemm(const float* __restrict__ fcb, float* __restrict__ out)
{
    extern __shared__ __align__(16) char smraw[];
    const uint32_t sbase = smem_u32(smraw);
    const int b = blockIdx.z;
    const __half* A  = g_QCh + (size_t)b * Lc * FP;
    const __half* Bw = g_W2Th + (size_t)b * Dc * FP;
    float* C = out + (size_t)b * Lc * Dc;

    const int m0 = blockIdx.y * 128;
    const int n0 = blockIdx.x * 128;

    float acc[4][4][4] = {};
    gemm_mainloop(A, Bw, FP, FP / 32, m0, n0, sbase, acc);

    const int tid = threadIdx.x;
    const int wid = tid >> 5;
    const int lane = tid & 31;
    const int g = lane >> 2;
    const int t = lane & 3;
    const int mw = (wid >> 2) * 64;
    const int nw = (wid & 3) * 32;

#pragma unroll
    for (int i = 0; i < 4; i++) {
        const int row0 = m0 + mw + 16 * i + g;
#pragma unroll
        for (int j = 0; j < 4; j++) {
            const int col = n0 + nw + 8 * j + 2 * t;
            float2 bv = *(const float2*)(fcb + col);
            float2 o0, o1;
            o0.x = acc[i][j][0] + bv.x;  o0.y = acc[i][j][1] + bv.y;
            o1.x = acc[i][j][2] + bv.x;  o1.y = acc[i][j][3] + bv.y;
            *(float2*)(C + (size_t)row0 * Dc + col) = o0;
            *(float2*)(C + (size_t)(row0 + 8) * Dc + col) = o1;
        }
    }
}

// ============================================================================
// launch
// ============================================================================
extern "C" void kernel_launch(void* const* d_in, const int* in_sizes, int n_in,
                              void* d_out, int out_size)
{
    const float* query = (const float*)d_in[0];
    const float* key   = (const float*)d_in[1];
    const float* value = (const float*)d_in[2];
    const float* pos   = (const float*)d_in[3];
    const float* Wq    = (const float*)d_in[4];
    const float* bq    = (const float*)d_in[5];
    const float* Wk    = (const float*)d_in[6];
    const float* bk    = (const float*)d_in[7];
    const float* Wv    = (const float*)d_in[8];
    const float* bv    = (const float*)d_in[9];
    const float* gK    = (const float*)d_in[10];
    const float* betaK = (const float*)d_in[11];
    const float* gV    = (const float*)d_in[12];
    const float* betaV = (const float*)d_in[13];
    const float* fcW   = (const float*)d_in[14];
    const float* fcb   = (const float*)d_in[15];

    float* att_out  = (float*)d_out;
    float* attn_out = att_out + ATT_ELEMS;

    cudaFuncSetAttribute(proj_fused, cudaFuncAttributeMaxDynamicSharedMemorySize, SMEM_PROJ);
    cudaFuncSetAttribute(out_gemm,  cudaFuncAttributeMaxDynamicSharedMemorySize, SMEM_MAIN);
    cudaFuncSetAttribute(attn_mma,  cudaFuncAttributeMaxDynamicSharedMemorySize, SMEM_ATTN);

    // 0) convert inputs + weights to fp16
    xcvt<<<dim3((unsigned)(BLD / 4 / 256), 3), 256>>>(query, key, value);
    wcvt<<<dim3(Dc * Dc / 4 / 256, 3), 256>>>(Wq, Wk, Wv);
    // 1) fused projections + LN + concat (fp16 MMA, fp32 accum)
    proj_fused<<<dim3(4, 256, 3), 256, SMEM_PROJ>>>(bq, bk, bv,
                                                     gK, betaK, gV, betaV, pos);
    // 2) attn partials via fp16 MMA + swizzled ldmatrix.trans (deterministic)
    attn_mma<<<dim3(NSPLIT, Hc, Bc), 256, SMEM_ATTN>>>();
    // 3) reduce + scale -> attn output
    attn_reduce<<<(unsigned)((ATTN_ELEMS + 255) / 256), 256>>>(attn_out);
    // 4) fold attn into fc weights (fp16 out)
    w2t_kernel<<<dim3(8, Bc * Hc), 256>>>(attn_out, fcW);
    // 5) output GEMM (fp16 MMA), batched over z
    out_gemm<<<dim3(4, 64, Bc), 256, SMEM_MAIN>>>(fcb, att_out);
}

// round 15
// speedup vs baseline: 1.0813x; 1.0132x over previous
#include <cuda_runtime.h>
#include <cuda_fp16.h>
#include <cstdint>

// ---------------- problem constants ----------------
#define Bc 4
#define Lc 8192
#define Dc 512
#define Hc 8
#define DKc 64
#define Ec 65           // DK + PD
#define Fc 520          // H * E
#define FP 544          // padded F (multiple of 32)
#define EHH 72          // padded per-head width (halfs, 144B = 9x16B)
#define NSPLIT 16
#define LCHUNK (Lc / NSPLIT)   // 512

#define ATT_ELEMS  ((size_t)Bc * Lc * Dc)
#define ATTN_ELEMS ((size_t)Bc * Hc * Ec * Ec)
#define BLD ((size_t)Bc * Lc * Dc)

// ---------------- scratch (device globals; no allocs allowed) ----------------
__device__ __half g_Wh[3][(size_t)Dc * Dc];          // fp16 Wq/Wk/Wv
__device__ __half g_QCh[(size_t)Bc * Lc * FP];       // concat q, fp16, pad zeroed
__device__ __half g_KHh[(size_t)Bc * Hc * Lc * EHH]; // LN'd k, fp16 (rounded once)
__device__ __half g_VHh[(size_t)Bc * Hc * Lc * EHH]; // LN'd v, fp16
__device__ float  g_part[(size_t)Bc * Hc * NSPLIT * Ec * Ec];
__device__ __half g_W2Th[(size_t)Bc * Dc * FP];      // folded fc weights, fp16

// ============================================================================
// helpers
// ============================================================================
__device__ __forceinline__ uint32_t smem_u32(const void* p) {
    uint32_t a;
    asm("{ .reg .u64 t; cvta.to.shared.u64 t, %1; cvt.u32.u64 %0, t; }" : "=r"(a) : "l"(p));
    return a;
}
__device__ __forceinline__ void cp16(uint32_t dst, const void* src) {
    asm volatile("cp.async.ca.shared.global [%0], [%1], 16;" :: "r"(dst), "l"(src));
}
#define CP_COMMIT() asm volatile("cp.async.commit_group;" ::: "memory")
#define CP_WAIT0()  asm volatile("cp.async.wait_group 0;" ::: "memory")
#define CP_WAIT1()  asm volatile("cp.async.wait_group 1;" ::: "memory")

__device__ __forceinline__ void mma_f16(float c[4], const uint32_t a[4], const uint32_t b[2]) {
    asm volatile(
        "mma.sync.aligned.m16n8k16.row.col.f32.f16.f16.f32 "
        "{%0,%1,%2,%3}, {%4,%5,%6,%7}, {%8,%9}, {%0,%1,%2,%3};"
        : "+f"(c[0]), "+f"(c[1]), "+f"(c[2]), "+f"(c[3])
        : "r"(a[0]), "r"(a[1]), "r"(a[2]), "r"(a[3]), "r"(b[0]), "r"(b[1]));
}
__device__ __forceinline__ uint32_t packh2(float a, float b) {
    __half2 h = __floats2half2_rn(a, b);
    return *(uint32_t*)&h;
}
#define LDSM_X4(r0, r1, r2, r3, addr) \
    asm volatile("ldmatrix.sync.aligned.m8n8.x4.shared.b16 {%0,%1,%2,%3}, [%4];" \
        : "=r"(r0), "=r"(r1), "=r"(r2), "=r"(r3) : "r"(addr))
#define LDSM_X4_T(r0, r1, r2, r3, addr) \
    asm volatile("ldmatrix.sync.aligned.m8n8.x4.trans.shared.b16 {%0,%1,%2,%3}, [%4];" \
        : "=r"(r0), "=r"(r1), "=r"(r2), "=r"(r3) : "r"(addr))
#define LDSM_X2_T(r0, r1, addr) \
    asm volatile("ldmatrix.sync.aligned.m8n8.x2.trans.shared.b16 {%0,%1}, [%2];" \
        : "=r"(r0), "=r"(r1) : "r"(addr))

// ============================================================================
// fp16 GEMM core: 128x128 CTA tile, 256 thr (8 warps, warp 64x32), K-block 32,
// 3-stage smem, fragments via ldmatrix.x4.
// ============================================================================
#define SSTRH 40                        // smem row stride in halfs (80B)
#define ATILEH (128 * SSTRH)            // 5120 halfs per operand per stage
#define STAGEH (2 * ATILEH)             // 10240 halfs per stage
#define NSTAGE 3
#define SMEM_MAIN (NSTAGE * STAGEH * 2) // 61440 bytes
#define SMEM_PROJ (128 * 132 * 4)       // 67584 bytes (epilogue staging)

__device__ __forceinline__ void gemm_compute_block(
    uint32_t abase, uint32_t bbase, uint32_t aoff, uint32_t boff,
    float acc[4][4][4])
{
#pragma unroll
    for (int kk = 0; kk < 32; kk += 16) {
        uint32_t af[4][4];
#pragma unroll
        for (int i = 0; i < 4; i++)
            LDSM_X4(af[i][0], af[i][1], af[i][2], af[i][3],
                    abase + aoff + (uint32_t)((16 * i) * SSTRH + kk) * 2u);
        uint32_t bf[4][2];
#pragma unroll
        for (int jj = 0; jj < 2; jj++)
            LDSM_X4(bf[2 * jj][0], bf[2 * jj][1], bf[2 * jj + 1][0], bf[2 * jj + 1][1],
                    bbase + boff + (uint32_t)((16 * jj) * SSTRH + kk) * 2u);
#pragma unroll
        for (int i = 0; i < 4; i++)
#pragma unroll
            for (int j = 0; j < 4; j++)
                mma_f16(acc[i][j], af[i], bf[j]);
    }
}

// ---- variant 1: both operands fp16 via cp.async (out_gemm) ----
__device__ __forceinline__ void gemm_copy_stage_hh(
    const __half* __restrict__ A, const __half* __restrict__ Bw,
    int lda, int m0, int n0, int kb, uint32_t sbase, int r0, int c)
{
    const int s = kb % NSTAGE;
    const int k0 = kb << 5;
    uint32_t as = sbase + (uint32_t)(s * STAGEH) * 2u;
    uint32_t bs = as + (uint32_t)ATILEH * 2u;
#pragma unroll
    for (int rr = 0; rr < 2; rr++) {
        const int row = r0 + rr * 64;
        uint32_t doff = (uint32_t)(row * SSTRH + c * 8) * 2u;
        cp16(as + doff, A + (size_t)(m0 + row) * lda + k0 + c * 8);
        cp16(bs + doff, Bw + (size_t)(n0 + row) * lda + k0 + c * 8);
    }
}

__device__ __forceinline__ void gemm_mainloop_hh(
    const __half* __restrict__ A, const __half* __restrict__ Bw,
    int lda, int NKB, int m0, int n0,
    uint32_t sbase, float acc[4][4][4])
{
    const int tid = threadIdx.x;
    const int wid = tid >> 5;
    const int lane = tid & 31;
    const int mw = (wid >> 2) * 64;
    const int nw = (wid & 3) * 32;
    const int r0 = tid >> 2;
    const int cc = tid & 3;

    const int rA = (lane & 7) + (lane & 8);
    const int cA = (lane & 16) >> 1;
    const int rB = (lane & 7) + ((lane & 16) >> 1);
    const int cB = (lane & 8);
    const uint32_t aoff = (uint32_t)((mw + rA) * SSTRH + cA) * 2u;
    const uint32_t boff = (uint32_t)((nw + rB) * SSTRH + cB) * 2u;

    gemm_copy_stage_hh(A, Bw, lda, m0, n0, 0, sbase, r0, cc);
    CP_COMMIT();
    gemm_copy_stage_hh(A, Bw, lda, m0, n0, 1, sbase, r0, cc);
    CP_COMMIT();

#pragma unroll 1
    for (int kb = 0; kb < NKB; kb++) {
        if (kb + 1 < NKB) { CP_WAIT1(); } else { CP_WAIT0(); }
        __syncthreads();
        if (kb + 2 < NKB) {
            gemm_copy_stage_hh(A, Bw, lda, m0, n0, kb + 2, sbase, r0, cc);
            CP_COMMIT();
        }
        const uint32_t abase = sbase + (uint32_t)((kb % NSTAGE) * STAGEH) * 2u;
        gemm_compute_block(abase, abase + (uint32_t)ATILEH * 2u, aoff, boff, acc);
    }
}

// ---- variant 2: A fp32 via LDG+cvt+STS (register-staged), B fp16 cp.async ----
__device__ __forceinline__ void gemm_mainloop_f32a(
    const float* __restrict__ A, const __half* __restrict__ Bw,
    int ldaA, int ldaB, int NKB, int m0, int n0,
    uint32_t sbase, float acc[4][4][4])
{
    const int tid = threadIdx.x;
    const int wid = tid >> 5;
    const int lane = tid & 31;
    const int mw = (wid >> 2) * 64;
    const int nw = (wid & 3) * 32;
    const int arow = tid >> 1;            // A copy row 0..127
    const int acolg = (tid & 1) << 4;     // 0 or 16 (halfs/floats)
    const int r0 = tid >> 2;              // B copy row
    const int cc = tid & 3;

    const int rA = (lane & 7) + (lane & 8);
    const int cA = (lane & 16) >> 1;
    const int rB = (lane & 7) + ((lane & 16) >> 1);
    const int cB = (lane & 8);
    const uint32_t aoff = (uint32_t)((mw + rA) * SSTRH + cA) * 2u;
    const uint32_t boff = (uint32_t)((nw + rB) * SSTRH + cB) * 2u;

    const float* asrc = A + (size_t)(m0 + arow) * ldaA + acolg;
    const uint32_t adst = sbase + (uint32_t)(arow * SSTRH + acolg) * 2u;

    float4 a4[4];
    // prologue: LDG A(0), cp.async B(0), B(1)
#pragma unroll
    for (int i = 0; i < 4; i++) a4[i] = *(const float4*)(asrc + 4 * i);
    {
        uint32_t bs = sbase + (uint32_t)ATILEH * 2u;
#pragma unroll
        for (int rr = 0; rr < 2; rr++) {
            const int row = r0 + rr * 64;
            cp16(bs + (uint32_t)(row * SSTRH + cc * 8) * 2u,
                 Bw + (size_t)(n0 + row) * ldaB + cc * 8);
        }
        CP_COMMIT();
        bs += (uint32_t)STAGEH * 2u;
#pragma unroll
        for (int rr = 0; rr < 2; rr++) {
            const int row = r0 + rr * 64;
            cp16(bs + (uint32_t)(row * SSTRH + cc * 8) * 2u,
                 Bw + (size_t)(n0 + row) * ldaB + 32 + cc * 8);
        }
        CP_COMMIT();
    }

#pragma unroll 1
    for (int kb = 0; kb < NKB; kb++) {
        // STS A(kb) from registers (cvt to fp16)
        {
            uint32_t d = adst + (uint32_t)((kb % NSTAGE) * STAGEH) * 2u;
            uint4 p0, p1;
            p0.x = packh2(a4[0].x, a4[0].y); p0.y = packh2(a4[0].z, a4[0].w);
            p0.z = packh2(a4[1].x, a4[1].y); p0.w = packh2(a4[1].z, a4[1].w);
            p1.x = packh2(a4[2].x, a4[2].y); p1.y = packh2(a4[2].z, a4[2].w);
            p1.z = packh2(a4[3].x, a4[3].y); p1.w = packh2(a4[3].z, a4[3].w);
            asm volatile("st.shared.v4.b32 [%0], {%1,%2,%3,%4};"
                         :: "r"(d), "r"(p0.x), "r"(p0.y), "r"(p0.z), "r"(p0.w));
            asm volatile("st.shared.v4.b32 [%0], {%1,%2,%3,%4};"
                         :: "r"(d + 16u), "r"(p1.x), "r"(p1.y), "r"(p1.z), "r"(p1.w));
        }
        // LDG A(kb+1) — consumed next iteration (latency hidden by compute)
        if (kb + 1 < NKB) {
            const float* s = asrc + ((kb + 1) << 5);
#pragma unroll
            for (int i = 0; i < 4; i++) a4[i] = *(const float4*)(s + 4 * i);
        }
        if (kb + 1 < NKB) { CP_WAIT1(); } else { CP_WAIT0(); }
        __syncthreads();
        // issue B(kb+2)
        if (kb + 2 < NKB) {
            uint32_t bs = sbase + (uint32_t)(((kb + 2) % NSTAGE) * STAGEH + ATILEH) * 2u;
            const int k0 = (kb + 2) << 5;
#pragma unroll
            for (int rr = 0; rr < 2; rr++) {
                const int row = r0 + rr * 64;
                cp16(bs + (uint32_t)(row * SSTRH + cc * 8) * 2u,
                     Bw + (size_t)(n0 + row) * ldaB + k0 + cc * 8);
            }
            CP_COMMIT();
        }
        const uint32_t abase = sbase + (uint32_t)((kb % NSTAGE) * STAGEH) * 2u;
        gemm_compute_block(abase, abase + (uint32_t)ATILEH * 2u, aoff, boff, acc);
    }
}

// ============================================================================
// Kernel W: pre-round Wq/Wk/Wv to fp16
// ============================================================================
__global__ void wcvt(const float* __restrict__ Wq, const float* __restrict__ Wk,
                     const float* __restrict__ Wv)
{
    const int op = blockIdx.y;
    const float* W = (op == 0) ? Wq : (op == 1) ? Wk : Wv;
    const size_t i4 = (size_t)blockIdx.x * 256 + threadIdx.x;
    float4 v = ((const float4*)W)[i4];
    __half2* dst = (__half2*)(g_Wh[op] + i4 * 4);
    dst[0] = __floats2half2_rn(v.x, v.y);
    dst[1] = __floats2half2_rn(v.z, v.w);
}

// ============================================================================
// Kernel A: fused projection + LN + concat.  grid (4, 256, 3), 256 thr.
// A operand read as fp32 directly from inputs (no pre-convert pass).
// ============================================================================
#define CSTR 132

__global__ void __launch_bounds__(256, 2)
proj_fused(const float* __restrict__ Xq, const float* __restrict__ Xk,
           const float* __restrict__ Xv,
           const float* __restrict__ bq, const float* __restrict__ bk,
           const float* __restrict__ bv,
           const float* __restrict__ gK, const float* __restrict__ betaK,
           const float* __restrict__ gV, const float* __restrict__ betaV,
           const float* __restrict__ pos)
{
    extern __shared__ __align__(16) char smraw[];
    float* smf = (float*)smraw;
    const uint32_t sbase = smem_u32(smraw);
    const int mode = blockIdx.z;
    const float* A = (mode == 0) ? Xq : (mode == 1) ? Xk : Xv;
    const __half* W = g_Wh[mode];
    const float* bias = (mode == 0) ? bq : (mode == 1) ? bk : bv;
    const float* gamm = (mode == 1) ? gK : gV;
    const float* beta = (mode == 1) ? betaK : betaV;

    const int m0 = blockIdx.y * 128;
    const int n0 = blockIdx.x * 128;

    float acc[4][4][4] = {};
    gemm_mainloop_f32a(A, W, Dc, Dc, Dc / 32, m0, n0, sbase, acc);

    // ---- stage tile (+bias) into smem as fp32 ----
    __syncthreads();
    const int tid = threadIdx.x;
    const int wid = tid >> 5;
    const int lane = tid & 31;
    const int g = lane >> 2;
    const int t = lane & 3;
    const int mw = (wid >> 2) * 64;
    const int nw = (wid & 3) * 32;

#pragma unroll
    for (int i = 0; i < 4; i++) {
        const int r0 = mw + 16 * i + g;
#pragma unroll
        for (int j = 0; j < 4; j++) {
            const int col = nw + 8 * j + 2 * t;
            float2 bv2 = *(const float2*)(bias + n0 + col);
            smf[r0 * CSTR + col]       = acc[i][j][0] + bv2.x;
            smf[r0 * CSTR + col + 1]   = acc[i][j][1] + bv2.y;
            smf[(r0 + 8) * CSTR + col]     = acc[i][j][2] + bv2.x;
            smf[(r0 + 8) * CSTR + col + 1] = acc[i][j][3] + bv2.y;
        }
    }
    __syncthreads();

    // ---- per-row epilogue: 8 warps x 16 rows ----
    for (int rr = 0; rr < 16; rr++) {
        const int r = wid * 16 + rr;
        const int m = m0 + r;                 // = b*L + l
        const int b = m >> 13, l = m & (Lc - 1);
        const float pv = pos[m];
#pragma unroll
        for (int hh = 0; hh < 2; hh++) {
            const int h = (n0 >> 6) + hh;
            float x0 = smf[r * CSTR + 64 * hh + lane];
            float x1 = smf[r * CSTR + 64 * hh + lane + 32];
            if (mode == 0) {
                __half* qrow = &g_QCh[(size_t)m * FP + h * Ec];
                if (lane == 0) qrow[0] = __float2half_rn(pv);
                qrow[1 + lane] = __float2half_rn(x0);
                qrow[1 + lane + 32] = __float2half_rn(x1);
                if (hh == 1 && n0 == 384 && lane < (FP - Fc))
                    g_QCh[(size_t)m * FP + Fc + lane] = __float2half_rn(0.0f);
            } else {
                float s = x0 + x1, sq = x0 * x0 + x1 * x1;
#pragma unroll
                for (int off = 16; off; off >>= 1) {
                    s  += __shfl_xor_sync(0xffffffffu, s,  off);
                    sq += __shfl_xor_sync(0xffffffffu, sq, off);
                }
                float mean = s * (1.0f / 64.0f);
                float var = sq * (1.0f / 64.0f) - mean * mean;
                float rstd = rsqrtf(var + 1e-5f);
                float y0 = (x0 - mean) * rstd * gamm[h * DKc + lane] + beta[h * DKc + lane];
                float y1 = (x1 - mean) * rstd * gamm[h * DKc + lane + 32] + beta[h * DKc + lane + 32];
                __half* orow = ((mode == 1) ? g_KHh : g_VHh) +
                               (((size_t)b * Hc + h) * Lc + l) * EHH;
                if (lane == 0) orow[0] = __float2half_rn(pv);
                orow[1 + lane] = __float2half_rn(y0);
                orow[1 + lane + 32] = __float2half_rn(y1);
                if (lane < (EHH - Ec)) orow[Ec + lane] = __float2half_rn(0.0f); // pad 65..71
            }
        }
    }
}

// ============================================================================
// Kernel B: attn partials via fp16 MMA + ldmatrix.trans, XOR-swizzled smem.
// ============================================================================
#define AST 128                         // smem row pitch (halfs) = 256B
#define ATILE_H (32 * AST)
#define ASTG (2 * ATILE_H)
#define ANST 3
#define SMEM_ATTN (ANST * ASTG * 2)     // 49152 bytes

__global__ void __launch_bounds__(256, 2)
attn_mma()
{
    extern __shared__ __align__(16) __half smha[];
    const uint32_t sbase = smem_u32(smha);
    const int split = blockIdx.x, h = blockIdx.y, b = blockIdx.z;
    const int tid = threadIdx.x;
    const int wid = tid >> 5, lane = tid & 31;
    const int g = lane >> 2, t = lane & 3;
    const int mw = (wid >> 2) * 48;
    const int nw = (wid & 3) * 24;
    const int NKB = LCHUNK / 32;
    const int s7 = lane & 7;

    const __half* Kb = g_KHh + (((size_t)b * Hc + h) * Lc + (size_t)split * LCHUNK) * EHH;
    const __half* Vb = g_VHh + (((size_t)b * Hc + h) * Lc + (size_t)split * LCHUNK) * EHH;

    for (int i = tid; i < ANST * ASTG / 8; i += 256)
        ((uint4*)smha)[i] = make_uint4(0, 0, 0, 0);
    __syncthreads();

    auto issue = [&](int kb) {
        const int s = kb % ANST;
        const int l0 = kb << 5;
        uint32_t base = sbase + (uint32_t)(s * ASTG) * 2u;
#pragma unroll
        for (int c = 0; c < 3; c++) {
            int idx = tid + (c << 8);
            if (idx < 576) {
                int op = idx >= 288;
                int i2 = op ? idx - 288 : idx;
                int row = i2 / 9, ch = i2 % 9;
                const __half* src = (op ? Vb : Kb) + (size_t)(l0 + row) * EHH + ch * 8;
                uint32_t dst = base + (uint32_t)(op * ATILE_H + row * AST) * 2u
                             + (uint32_t)((ch ^ (row & 7)) * 16);
                cp16(dst, src);
            }
        }
        CP_COMMIT();
    };

    issue(0);
    issue(1);

    const int arow = (lane & 7) + ((lane & 16) >> 1);
    const int acol = (lane & 8);
    const int brow = (lane & 7) + (lane & 8);
    const int bcol = (lane & 16) >> 1;

    uint32_t achk[3];
#pragma unroll
    for (int i = 0; i < 3; i++)
        achk[i] = (uint32_t)((((mw + 16 * i + acol) >> 3) ^ s7) * 16);
    const uint32_t bchk4 = (uint32_t)((((nw + bcol) >> 3) ^ s7) * 16);
    const uint32_t bchk2 = (uint32_t)((((nw + 16) >> 3) ^ s7) * 16);

    float acc[3][3][4] = {};

#pragma unroll 1
    for (int kb = 0; kb < NKB; kb++) {
        if (kb + 1 < NKB) { CP_WAIT1(); } else { CP_WAIT0(); }
        __syncthreads();
        if (kb + 2 < NKB) issue(kb + 2);

        const uint32_t kbase = sbase + (uint32_t)((kb % ANST) * ASTG) * 2u;
        const uint32_t vbase = kbase + (uint32_t)ATILE_H * 2u;
#pragma unroll
        for (int kk = 0; kk < 32; kk += 16) {
            uint32_t af[3][4];
#pragma unroll
            for (int i = 0; i < 3; i++)
                LDSM_X4_T(af[i][0], af[i][1], af[i][2], af[i][3],
                          kbase + (uint32_t)((kk + arow) * AST) * 2u + achk[i]);
            uint32_t bf[3][2];
            LDSM_X4_T(bf[0][0], bf[0][1], bf[1][0], bf[1][1],
                      vbase + (uint32_t)((kk + brow) * AST) * 2u + bchk4);
            LDSM_X2_T(bf[2][0], bf[2][1],
                      vbase + (uint32_t)((kk + brow) * AST) * 2u + bchk2);
#pragma unroll
            for (int i = 0; i < 3; i++)
#pragma unroll
                for (int j = 0; j < 3; j++)
                    mma_f16(acc[i][j], af[i], bf[j]);
        }
    }

    float* out = &g_part[(((size_t)b * Hc + h) * NSPLIT + split) * Ec * Ec];
#pragma unroll
    for (int i = 0; i < 3; i++) {
        const int m = mw + 16 * i + g;
#pragma unroll
        for (int j = 0; j < 3; j++) {
            const int n = nw + 8 * j + 2 * t;
            if (m < Ec) {
                if (n < Ec)     out[m * Ec + n]     = acc[i][j][0];
                if (n + 1 < Ec) out[m * Ec + n + 1] = acc[i][j][1];
            }
            if (m + 8 < Ec) {
                if (n < Ec)     out[(m + 8) * Ec + n]     = acc[i][j][2];
                if (n + 1 < Ec) out[(m + 8) * Ec + n + 1] = acc[i][j][3];
            }
        }
    }
}

// ============================================================================
// Kernel C: reduce partials, scale by 1/L
// ============================================================================
__global__ void attn_reduce(float* __restrict__ attn_out)
{
    const size_t idx = (size_t)blockIdx.x * blockDim.x + threadIdx.x;
    if (idx >= ATTN_ELEMS) return;
    const size_t bh = idx / (Ec * Ec);
    const size_t de = idx % (Ec * Ec);
    float s = 0.0f;
#pragma unroll
    for (int sp = 0; sp < NSPLIT; sp++)
        s += g_part[(bh * NSPLIT + sp) * (Ec * Ec) + de];
    attn_out[idx] = s * (1.0f / (float)Lc);
}

// ============================================================================
// Kernel D: W2Th[b,o,h*65+d] = sum_e attn[b,h,d,e]*fcW[o,h*65+e]   (fp16 out)
// ============================================================================
__global__ void __launch_bounds__(256)
w2t_kernel(const float* __restrict__ attn, const float* __restrict__ fcW)
{
    const int og = blockIdx.x;
    const int bh = blockIdx.y;
    const int b = bh >> 3, h = bh & 7;
    __shared__ float sa[Ec * 68];
    __shared__ float sw[64 * 66];
    const int tid = threadIdx.x;

    for (int i = tid; i < Ec * Ec; i += 256) {
        int d = i / Ec, e = i % Ec;
        sa[e * 68 + d] = attn[((size_t)bh * Ec + d) * Ec + e];
    }
    for (int i = tid; i < 64 * Ec; i += 256) {
        int o = i / Ec, e = i % Ec;
        sw[o * 66 + e] = fcW[(size_t)(og * 64 + o) * Fc + h * Ec + e];
    }
    __syncthreads();

    for (int idx = tid; idx < 64 * Ec; idx += 256) {
        int o = idx / Ec, d = idx % Ec;
        const float* wr = &sw[o * 66];
        float s = 0.0f;
#pragma unroll
        for (int e = 0; e < Ec; e++) s += wr[e] * sa[e * 68 + d];
        g_W2Th[((size_t)b * Dc + og * 64 + o) * FP + h * Ec + d] = __float2half_rn(s);
    }
    if (h == 0) {
        for (int i = tid; i < 64 * (FP - Fc); i += 256) {
            int o = og * 64 + i / (FP - Fc), cc = Fc + i % (FP - Fc);
            g_W2Th[((size_t)b * Dc + o) * FP + cc] = __float2half_rn(0.0f);
        }
    }
}

// ============================================================================
// Kernel E: out[b] = QCh[b] @ W2Th[b]^T + fcb.  grid (4, 64, 4), 256 thr.
// ============================================================================
__global__ void __launch_bounds__(256, 2)
out_gemm(const float* __restrict__ fcb, float* __restrict__ out)
{
    extern __shared__ __align__(16) char smraw[];
    const uint32_t sbase = smem_u32(smraw);
    const int b = blockIdx.z;
    const __half* A  = g_QCh + (size_t)b * Lc * FP;
    const __half* Bw = g_W2Th + (size_t)b * Dc * FP;
    float* C = out + (size_t)b * Lc * Dc;

    const int m0 = blockIdx.y * 128;
    const int n0 = blockIdx.x * 128;

    float acc[4][4][4] = {};
    gemm_mainloop_hh(A, Bw, FP, FP / 32, m0, n0, sbase, acc);

    const int tid = threadIdx.x;
    const int wid = tid >> 5;
    const int lane = tid & 31;
    const int g = lane >> 2;
    const int t = lane & 3;
    const int mw = (wid >> 2) * 64;
    const int nw = (wid & 3) * 32;

#pragma unroll
    for (int i = 0; i < 4; i++) {
        const int row0 = m0 + mw + 16 * i + g;
#pragma unroll
        for (int j = 0; j < 4; j++) {
            const int col = n0 + nw + 8 * j + 2 * t;
            float2 bv = *(const float2*)(fcb + col);
            float2 o0, o1;
            o0.x = acc[i][j][0] + bv.x;  o0.y = acc[i][j][1] + bv.y;
            o1.x = acc[i][j][2] + bv.x;  o1.y = acc[i][j][3] + bv.y;
            *(float2*)(C + (size_t)row0 * Dc + col) = o0;
            *(float2*)(C + (size_t)(row0 + 8) * Dc + col) = o1;
        }
    }
}

// ============================================================================
// launch
// ============================================================================
extern "C" void kernel_launch(void* const* d_in, const int* in_sizes, int n_in,
                              void* d_out, int out_size)
{
    const float* query = (const float*)d_in[0];
    const float* key   = (const float*)d_in[1];
    const float* value = (const float*)d_in[2];
    const float* pos   = (const float*)d_in[3];
    const float* Wq    = (const float*)d_in[4];
    const float* bq    = (const float*)d_in[5];
    const float* Wk    = (const float*)d_in[6];
    const float* bk    = (const float*)d_in[7];
    const float* Wv    = (const float*)d_in[8];
    const float* bv    = (const float*)d_in[9];
    const float* gK    = (const float*)d_in[10];
    const float* betaK = (const float*)d_in[11];
    const float* gV    = (const float*)d_in[12];
    const float* betaV = (const float*)d_in[13];
    const float* fcW   = (const float*)d_in[14];
    const float* fcb   = (const float*)d_in[15];

    float* att_out  = (float*)d_out;
    float* attn_out = att_out + ATT_ELEMS;

    cudaFuncSetAttribute(proj_fused, cudaFuncAttributeMaxDynamicSharedMemorySize, SMEM_PROJ);
    cudaFuncSetAttribute(out_gemm,  cudaFuncAttributeMaxDynamicSharedMemorySize, SMEM_MAIN);
    cudaFuncSetAttribute(attn_mma,  cudaFuncAttributeMaxDynamicSharedMemorySize, SMEM_ATTN);

    // 0) pre-round weights to fp16 (inputs converted in-GEMM now)
    wcvt<<<dim3(Dc * Dc / 4 / 256, 3), 256>>>(Wq, Wk, Wv);
    // 1) fused projections + LN + concat (fp16 MMA, fp32 accum, fp32 A in)
    proj_fused<<<dim3(4, 256, 3), 256, SMEM_PROJ>>>(query, key, value,
                                                     bq, bk, bv,
                                                     gK, betaK, gV, betaV, pos);
    // 2) attn partials via fp16 MMA + swizzled ldmatrix.trans (deterministic)
    attn_mma<<<dim3(NSPLIT, Hc, Bc), 256, SMEM_ATTN>>>();
    // 3) reduce + scale -> attn output
    attn_reduce<<<(unsigned)((ATTN_ELEMS + 255) / 256), 256>>>(attn_out);
    // 4) fold attn into fc weights (fp16 out)
    w2t_kernel<<<dim3(8, Bc * Hc), 256>>>(attn_out, fcW);
    // 5) output GEMM (fp16 MMA), batched over z
    out_gemm<<<dim3(4, 64, Bc), 256, SMEM_MAIN>>>(fcb, att_out);
}